// round 7
// baseline (speedup 1.0000x reference)
#include <cuda_runtime.h>
#include <cuda_fp16.h>
#include <cstdint>

// ---------------- problem constants ----------------
#define HSZ   2048
#define BATCH 4096
#define KDIM  4096   // COMBINED
#define NDIM  8192   // 4H

// ---------------- fp16 scratch (device globals; no allocs) ----------------
__device__ __half g_A[(size_t)BATCH * KDIM];   // combined [B, C] fp16 (h_prev | x_t)
__device__ __half g_W[(size_t)NDIM * KDIM];    // weights, rows permuted n' = 4h + g
__device__ float  g_bias[NDIM];                // bias, permuted

__device__ __forceinline__ uint32_t smem_to_u32(const void* p) {
    uint32_t a;
    asm("{ .reg .u64 t; cvta.to.shared.u64 t, %1; cvt.u32.u64 %0, t; }" : "=r"(a) : "l"(p));
    return a;
}
__device__ __forceinline__ void cp16(uint32_t dst, const void* src) {
    asm volatile("cp.async.cg.shared.global [%0], [%1], 16;\n" :: "r"(dst), "l"(src));
}
__device__ __forceinline__ void ldsm_x4(uint32_t* r, uint32_t addr) {
    asm volatile("ldmatrix.sync.aligned.m8n8.x4.shared.b16 {%0,%1,%2,%3}, [%4];"
                 : "=r"(r[0]), "=r"(r[1]), "=r"(r[2]), "=r"(r[3]) : "r"(addr));
}
__device__ __forceinline__ void mma16816(float* c, const uint32_t* a, const uint32_t* b) {
    asm volatile("mma.sync.aligned.m16n8k16.row.col.f32.f16.f16.f32 "
                 "{%0,%1,%2,%3}, {%4,%5,%6,%7}, {%8,%9}, {%0,%1,%2,%3};"
                 : "+f"(c[0]), "+f"(c[1]), "+f"(c[2]), "+f"(c[3])
                 : "r"(a[0]), "r"(a[1]), "r"(a[2]), "r"(a[3]), "r"(b[0]), "r"(b[1]));
}

// ---------------- pass 1: fp32 -> fp16 conversion ----------------
__global__ void conv_a_kernel(const float* __restrict__ x, const float* __restrict__ h) {
    int i4 = blockIdx.x * blockDim.x + threadIdx.x;
    int e = i4 << 2;
    int m = e >> 12, k = e & 4095;
    float4 v = (k < HSZ) ? *(const float4*)(h + (size_t)m * HSZ + k)
                         : *(const float4*)(x + (size_t)m * HSZ + (k - HSZ));
    __half2* dst = (__half2*)(g_A + e);
    dst[0] = __floats2half2_rn(v.x, v.y);
    dst[1] = __floats2half2_rn(v.z, v.w);
}

__global__ void conv_w_kernel(const float* __restrict__ Wf, const float* __restrict__ Wi,
                              const float* __restrict__ Wc, const float* __restrict__ Wo) {
    int i4 = blockIdx.x * blockDim.x + threadIdx.x;
    size_t e = (size_t)i4 << 2;
    int n = (int)(e >> 12), k = (int)(e & 4095);        // n' = 4h + g (permuted row)
    int g = n & 3, hh = n >> 2;
    const float* src = (g == 0) ? Wf : (g == 1) ? Wi : (g == 2) ? Wc : Wo;
    float4 v = *(const float4*)(src + (size_t)hh * KDIM + k);
    __half2* dst = (__half2*)(g_W + e);
    dst[0] = __floats2half2_rn(v.x, v.y);
    dst[1] = __floats2half2_rn(v.z, v.w);
}

__global__ void conv_b_kernel(const float* __restrict__ bf, const float* __restrict__ bi,
                              const float* __restrict__ bc, const float* __restrict__ bo) {
    int n = blockIdx.x * blockDim.x + threadIdx.x;
    if (n < NDIM) {
        int g = n & 3, hh = n >> 2;
        const float* src = (g == 0) ? bf : (g == 1) ? bi : (g == 2) ? bc : bo;
        g_bias[n] = src[hh];
    }
}

// ---------------- pass 2: mma.sync GEMM, mid-iter barrier, frag pipeline ----------------
// BM=BN=128, 128 threads (4 warps, 2x2 grid of 64x64 warp tiles), 2 CTAs/SM
#define BM 128
#define BN 128
#define KT 64                  // 4096 / 64
#define STAGES 3
#define STAGE_A 16384          // 128 rows x 128B
#define STAGE_BYTES 32768      // A 16KB + B 16KB
#define EPI_STRIDE 132         // floats per row (128 + 4 pad)
#define BIAS_OFF (STAGES * STAGE_BYTES)          // 98304
#define SMEM_TOTAL (BIAS_OFF + BN * 4)           // 98816 -> 2 CTAs/SM

#define NTHREADS 128

__device__ __forceinline__ float sigmoidf_(float x) { return 1.0f / (1.0f + __expf(-x)); }
__device__ __forceinline__ float tanhf_(float x)    { return 2.0f / (1.0f + __expf(-2.0f * x)) - 1.0f; }

// prefetch one kstep's fragments (A: 4x ldsm.x4, B: 4x ldsm.x4)
#define LDSM_FRAGS(dstA, dstB, sA, sB, kc) do {                                           \
    _Pragma("unroll")                                                                     \
    for (int _t = 0; _t < 4; _t++)                                                        \
        ldsm_x4((dstA)[_t], (sA) + aOff[_t] + (uint32_t)((((kc) + hi) ^ aSw[_t]) << 4));  \
    _Pragma("unroll")                                                                     \
    for (int _p = 0; _p < 4; _p++)                                                        \
        ldsm_x4((dstB)[_p], (sB) + bOff[_p] + (uint32_t)((((kc) + piece) ^ bSw[_p]) << 4)); \
} while (0)

#define MMA_BURST(a, b) do {                                    \
    _Pragma("unroll")                                           \
    for (int _t = 0; _t < 4; _t++)                              \
        _Pragma("unroll")                                       \
        for (int _p = 0; _p < 4; _p++) {                        \
            mma16816(acc[_t][2 * _p],     (a)[_t], &(b)[_p][0]);\
            mma16816(acc[_t][2 * _p + 1], (a)[_t], &(b)[_p][2]);\
        }                                                       \
} while (0)

__global__ __launch_bounds__(NTHREADS, 2)
void lstm_gemm_kernel(const float* __restrict__ c_prev, float* __restrict__ out) {
    extern __shared__ char smem[];
    uint32_t smem_u32 = smem_to_u32(smem);
    float* smemf = (float*)smem;
    int tid = threadIdx.x;
    int lane = tid & 31, wid = tid >> 5;
    int wm = wid & 1, wn = wid >> 1;          // 2 x 2 warp grid, 64x64 warp tiles

    int mt = blockIdx.x & 31;                 // M-fastest: W panel stays hot in L2
    int nt = blockIdx.x >> 5;                 // 0..63
    int m0 = mt * BM, n0 = nt * BN;

    if (tid < BN / 4)
        ((float4*)(smem + BIAS_OFF))[tid] = ((const float4*)(g_bias + n0))[tid];

    // ---- incremental cp.async addressing: 8 chunk patterns shared by A and B ----
    uint32_t off[8], dsto[8];                 // off in halves; dsto = swizzled stage offset
#pragma unroll
    for (int i = 0; i < 8; i++) {
        int ch = tid + (i << 7);              // 0..1023
        int r = ch >> 3, cc = ch & 7;
        off[i]  = (uint32_t)(r * KDIM + cc * 8);
        dsto[i] = (uint32_t)(r * 128 + ((cc ^ (r & 7)) << 4));
    }
    const __half* baseA = g_A + (size_t)m0 * KDIM;
    const __half* baseB = g_W + (size_t)n0 * KDIM;

    // ---- ldmatrix offsets ----
    int hi = lane >> 4;                       // A k-half select
    int piece = (lane >> 3) & 1;              // B k-half select
    uint32_t aOff[4]; int aSw[4];
#pragma unroll
    for (int t4 = 0; t4 < 4; t4++) {
        int r = wm * 64 + t4 * 16 + (lane & 15);
        aOff[t4] = (uint32_t)(r * 128);
        aSw[t4] = r & 7;
    }
    uint32_t bOff[4]; int bSw[4];
#pragma unroll
    for (int p = 0; p < 4; p++) {
        int n = wn * 64 + p * 16 + (lane & 7) + ((lane >> 4) << 3);
        bOff[p] = (uint32_t)(n * 128);
        bSw[p] = n & 7;
    }

    float acc[4][8][4];
#pragma unroll
    for (int a = 0; a < 4; a++)
#pragma unroll
        for (int b = 0; b < 8; b++)
#pragma unroll
            for (int c = 0; c < 4; c++) acc[a][b][c] = 0.0f;

    // ---- stage issue (16 cp.async per thread) ----
    auto issue_stage = [&](int k0h, uint32_t sOff) {
#pragma unroll
        for (int i = 0; i < 8; i++)
            cp16(smem_u32 + sOff + dsto[i], baseA + off[i] + k0h);
#pragma unroll
        for (int i = 0; i < 8; i++)
            cp16(smem_u32 + STAGE_A + sOff + dsto[i], baseB + off[i] + k0h);
        asm volatile("cp.async.commit_group;\n" ::: "memory");
    };

    // prologue: issue stages 0,1; make stage 0 visible; prime iter0 kstep0
    issue_stage(0, 0);
    issue_stage(64, STAGE_BYTES);
    asm volatile("cp.async.wait_group 1;\n" ::: "memory");
    __syncthreads();

    uint32_t fA[2][4][4], fB[2][4][4];
    LDSM_FRAGS(fA[0], fB[0], smem_u32, smem_u32 + STAGE_A, 0);

#pragma unroll 1
    for (int k = 0; k < KT; k++) {
        uint32_t sA  = smem_u32 + (uint32_t)(k % STAGES) * STAGE_BYTES;
        uint32_t sB  = sA + STAGE_A;
        uint32_t sAn = smem_u32 + (uint32_t)((k + 1) % STAGES) * STAGE_BYTES;
        uint32_t sBn = sAn + STAGE_A;

        // kstep 0: prefetch kstep1 -> [1]; compute [0]
        LDSM_FRAGS(fA[1], fB[1], sA, sB, 2);
        MMA_BURST(fA[0], fB[0]);

        // kstep 1: prefetch kstep2 -> [0]; compute [1]
        LDSM_FRAGS(fA[0], fB[0], sA, sB, 4);
        MMA_BURST(fA[1], fB[1]);

        // mid-iter pipeline point: stage k+1 complete + visible; slot (k-1)%3 free
        if (k + 1 < KT) {
            asm volatile("cp.async.wait_group 0;\n" ::: "memory");
            __syncthreads();
        }

        // kstep 2: prefetch kstep3 -> [1]; compute [0]
        LDSM_FRAGS(fA[1], fB[1], sA, sB, 6);
        MMA_BURST(fA[0], fB[0]);

        // kstep 3: prefetch next iter's kstep0 from stage k+1 -> [0];
        //          refill slot (k-1)%3 with stage k+2; compute [1]
        if (k + 1 < KT) LDSM_FRAGS(fA[0], fB[0], sAn, sBn, 0);
        if (k + 2 < KT) issue_stage((k + 2) * 64, (uint32_t)((k + 2) % STAGES) * STAGE_BYTES);
        MMA_BURST(fA[1], fB[1]);
    }

    // -------- epilogue: acc -> smem (transpose to n-contiguous) --------
    __syncthreads();   // all compute done; stage smem now reusable
#pragma unroll
    for (int t4 = 0; t4 < 4; t4++) {
#pragma unroll
        for (int p = 0; p < 4; p++) {
            int r0 = wm * 64 + t4 * 16 + (lane >> 2);
            int c0 = wn * 64 + p * 16 + (lane & 3) * 2;
            *(float2*)&smemf[r0 * EPI_STRIDE + c0]            = make_float2(acc[t4][2 * p][0], acc[t4][2 * p][1]);
            *(float2*)&smemf[(r0 + 8) * EPI_STRIDE + c0]      = make_float2(acc[t4][2 * p][2], acc[t4][2 * p][3]);
            *(float2*)&smemf[r0 * EPI_STRIDE + c0 + 8]        = make_float2(acc[t4][2 * p + 1][0], acc[t4][2 * p + 1][1]);
            *(float2*)&smemf[(r0 + 8) * EPI_STRIDE + c0 + 8]  = make_float2(acc[t4][2 * p + 1][2], acc[t4][2 * p + 1][3]);
        }
    }
    __syncthreads();

    // -------- fused LSTM: gates -> h_t, c_t --------
    int r = tid;                      // 0..127 (batch row within tile)
    int mrow = m0 + r;
    int hglob0 = nt * 32;             // this block's head range (BN/4 = 32 heads)
    const float* cpr = c_prev + (size_t)mrow * HSZ + hglob0;
    float* hout = out + (size_t)mrow * HSZ + hglob0;
    float* cout = out + (size_t)BATCH * HSZ + (size_t)mrow * HSZ + hglob0;
    const float* biasf = (const float*)(smem + BIAS_OFF);
#pragma unroll
    for (int g4 = 0; g4 < 8; g4++) {
        int hl = g4 * 4;                               // local head base
        float4 cp4 = *(const float4*)(cpr + hl);
        float cpv[4] = {cp4.x, cp4.y, cp4.z, cp4.w};
        float hv[4], cv[4];
#pragma unroll
        for (int j = 0; j < 4; j++) {
            const float* gt = &smemf[r * EPI_STRIDE + (hl + j) * 4];
            const float* bs = &biasf[(hl + j) * 4];
            float gf = gt[0] + bs[0];
            float gi = gt[1] + bs[1];
            float gc = gt[2] + bs[2];
            float go = gt[3] + bs[3];
            float f  = sigmoidf_(gf);
            float iv = sigmoidf_(gi);
            float ct = tanhf_(gc);
            float o  = sigmoidf_(go);
            float cn = fmaf(f, cpv[j], iv * ct);
            cv[j] = cn;
            hv[j] = o * tanhf_(cn);
        }
        *(float4*)(hout + hl) = make_float4(hv[0], hv[1], hv[2], hv[3]);
        *(float4*)(cout + hl) = make_float4(cv[0], cv[1], cv[2], cv[3]);
    }
}

// ---------------- launch ----------------
extern "C" void kernel_launch(void* const* d_in, const int* in_sizes, int n_in,
                              void* d_out, int out_size) {
    const float* x  = (const float*)d_in[0];
    const float* h  = (const float*)d_in[1];
    const float* c  = (const float*)d_in[2];
    const float* Wf = (const float*)d_in[3];
    const float* bf = (const float*)d_in[4];
    const float* Wi = (const float*)d_in[5];
    const float* bi = (const float*)d_in[6];
    const float* Wc = (const float*)d_in[7];
    const float* bc = (const float*)d_in[8];
    const float* Wo = (const float*)d_in[9];
    const float* bo = (const float*)d_in[10];
    float* out = (float*)d_out;

    conv_a_kernel<<<(BATCH * KDIM / 4) / 256, 256>>>(x, h);
    conv_w_kernel<<<(NDIM * KDIM / 4) / 256, 256>>>(Wf, Wi, Wc, Wo);
    conv_b_kernel<<<NDIM / 256, 256>>>(bf, bi, bc, bo);

    static int smem_set = 0;
    if (!smem_set) {
        cudaFuncSetAttribute(lstm_gemm_kernel,
                             cudaFuncAttributeMaxDynamicSharedMemorySize, SMEM_TOTAL);
        smem_set = 1;
    }
    lstm_gemm_kernel<<<(BATCH / BM) * (NDIM / BN), NTHREADS, SMEM_TOTAL>>>(c, out);
}

// round 8
// speedup vs baseline: 1.0386x; 1.0386x over previous
#include <cuda_runtime.h>
#include <cuda_fp16.h>
#include <cstdint>

// ---------------- problem constants ----------------
#define HSZ   2048
#define BATCH 4096
#define KDIM  4096   // COMBINED
#define NDIM  8192   // 4H

// ---------------- fp16 scratch (device globals; no allocs) ----------------
__device__ __half g_A[(size_t)BATCH * KDIM];   // combined [B, C] fp16 (h_prev | x_t)
__device__ __half g_W[(size_t)NDIM * KDIM];    // weights, rows permuted n' = 4h + g
__device__ float  g_bias[NDIM];                // bias, permuted

__device__ __forceinline__ uint32_t smem_to_u32(const void* p) {
    uint32_t a;
    asm("{ .reg .u64 t; cvta.to.shared.u64 t, %1; cvt.u32.u64 %0, t; }" : "=r"(a) : "l"(p));
    return a;
}
__device__ __forceinline__ void cp16(uint32_t dst, const void* src) {
    asm volatile("cp.async.cg.shared.global [%0], [%1], 16;\n" :: "r"(dst), "l"(src));
}
__device__ __forceinline__ void ldsm_x4(uint32_t* r, uint32_t addr) {
    asm volatile("ldmatrix.sync.aligned.m8n8.x4.shared.b16 {%0,%1,%2,%3}, [%4];"
                 : "=r"(r[0]), "=r"(r[1]), "=r"(r[2]), "=r"(r[3]) : "r"(addr));
}
__device__ __forceinline__ void mma16816(float* c, const uint32_t* a, const uint32_t* b) {
    asm volatile("mma.sync.aligned.m16n8k16.row.col.f32.f16.f16.f32 "
                 "{%0,%1,%2,%3}, {%4,%5,%6,%7}, {%8,%9}, {%0,%1,%2,%3};"
                 : "+f"(c[0]), "+f"(c[1]), "+f"(c[2]), "+f"(c[3])
                 : "r"(a[0]), "r"(a[1]), "r"(a[2]), "r"(a[3]), "r"(b[0]), "r"(b[1]));
}

// ---------------- pass 1: fp32 -> fp16 conversion ----------------
__global__ void conv_a_kernel(const float* __restrict__ x, const float* __restrict__ h) {
    int i4 = blockIdx.x * blockDim.x + threadIdx.x;
    int e = i4 << 2;
    int m = e >> 12, k = e & 4095;
    float4 v = (k < HSZ) ? *(const float4*)(h + (size_t)m * HSZ + k)
                         : *(const float4*)(x + (size_t)m * HSZ + (k - HSZ));
    __half2* dst = (__half2*)(g_A + e);
    dst[0] = __floats2half2_rn(v.x, v.y);
    dst[1] = __floats2half2_rn(v.z, v.w);
}

__global__ void conv_w_kernel(const float* __restrict__ Wf, const float* __restrict__ Wi,
                              const float* __restrict__ Wc, const float* __restrict__ Wo) {
    int i4 = blockIdx.x * blockDim.x + threadIdx.x;
    size_t e = (size_t)i4 << 2;
    int n = (int)(e >> 12), k = (int)(e & 4095);        // n' = 4h + g (permuted row)
    int g = n & 3, hh = n >> 2;
    const float* src = (g == 0) ? Wf : (g == 1) ? Wi : (g == 2) ? Wc : Wo;
    float4 v = *(const float4*)(src + (size_t)hh * KDIM + k);
    __half2* dst = (__half2*)(g_W + e);
    dst[0] = __floats2half2_rn(v.x, v.y);
    dst[1] = __floats2half2_rn(v.z, v.w);
}

__global__ void conv_b_kernel(const float* __restrict__ bf, const float* __restrict__ bi,
                              const float* __restrict__ bc, const float* __restrict__ bo) {
    int n = blockIdx.x * blockDim.x + threadIdx.x;
    if (n < NDIM) {
        int g = n & 3, hh = n >> 2;
        const float* src = (g == 0) ? bf : (g == 1) ? bi : (g == 2) ? bc : bo;
        g_bias[n] = src[hh];
    }
}

// ---------------- pass 2: mma.sync GEMM, slim-register frag pipeline ----------------
// BM=BN=128, 128 threads (4 warps, 2x2 grid of 64x64 warp tiles), 2 CTAs/SM
#define BM 128
#define BN 128
#define KT 64                  // 4096 / 64
#define STAGES 3
#define STAGE_A 16384          // 128 rows x 128B
#define STAGE_BYTES 32768      // A 16KB + B 16KB
#define EPI_STRIDE 132         // floats per row (128 + 4 pad)
#define BIAS_OFF (STAGES * STAGE_BYTES)          // 98304
#define SMEM_TOTAL (BIAS_OFF + BN * 4)           // 98816 -> 2 CTAs/SM

#define NTHREADS 128

__device__ __forceinline__ float sigmoidf_(float x) { return 1.0f / (1.0f + __expf(-x)); }
__device__ __forceinline__ float tanhf_(float x)    { return 2.0f / (1.0f + __expf(-2.0f * x)) - 1.0f; }

// prefetch one kstep's fragments: swizzle term collapses to one XOR per operand
#define LDSM_FRAGS(dstA, dstB, sA, sB, kc) do {                                   \
    uint32_t _ax = (uint32_t)((((kc) + hi) ^ swz) << 4);                          \
    uint32_t _bx = (uint32_t)((((kc) + piece) ^ swz) << 4);                       \
    ldsm_x4((dstA)[0], (sA) + a0 + 0 * 2048 + _ax);                               \
    ldsm_x4((dstA)[1], (sA) + a0 + 1 * 2048 + _ax);                               \
    ldsm_x4((dstA)[2], (sA) + a0 + 2 * 2048 + _ax);                               \
    ldsm_x4((dstA)[3], (sA) + a0 + 3 * 2048 + _ax);                               \
    ldsm_x4((dstB)[0], (sB) + b0 + 0 * 2048 + _bx);                               \
    ldsm_x4((dstB)[1], (sB) + b0 + 1 * 2048 + _bx);                               \
    ldsm_x4((dstB)[2], (sB) + b0 + 2 * 2048 + _bx);                               \
    ldsm_x4((dstB)[3], (sB) + b0 + 3 * 2048 + _bx);                               \
} while (0)

#define MMA_BURST(a, b) do {                                    \
    _Pragma("unroll")                                           \
    for (int _t = 0; _t < 4; _t++)                              \
        _Pragma("unroll")                                       \
        for (int _p = 0; _p < 4; _p++) {                        \
            mma16816(acc[_t][2 * _p],     (a)[_t], &(b)[_p][0]);\
            mma16816(acc[_t][2 * _p + 1], (a)[_t], &(b)[_p][2]);\
        }                                                       \
} while (0)

__global__ __launch_bounds__(NTHREADS, 2)
void lstm_gemm_kernel(const float* __restrict__ c_prev, float* __restrict__ out) {
    extern __shared__ char smem[];
    uint32_t smem_u32 = smem_to_u32(smem);
    float* smemf = (float*)smem;
    int tid = threadIdx.x;
    int lane = tid & 31, wid = tid >> 5;
    int wm = wid & 1, wn = wid >> 1;          // 2 x 2 warp grid, 64x64 warp tiles

    int mt = blockIdx.x & 31;                 // M-fastest: W panel stays hot in L2
    int nt = blockIdx.x >> 5;                 // 0..63
    int m0 = mt * BM, n0 = nt * BN;

    if (tid < BN / 4)
        ((float4*)(smem + BIAS_OFF))[tid] = ((const float4*)(g_bias + n0))[tid];

    // ---- cp.async addressing: arithmetic progression, 2 base offsets only ----
    // chunk i (i=0..7): row = (tid>>3) + 16*i, col-chunk = tid&7 (constant)
    uint32_t srcOff0 = (uint32_t)((tid >> 3) * KDIM + (tid & 7) * 8);              // halves
    uint32_t dst0    = (uint32_t)((tid >> 3) * 128 + (((tid & 7) ^ ((tid >> 3) & 7)) << 4));
    const __half* baseA = g_A + (size_t)m0 * KDIM;
    const __half* baseB = g_W + (size_t)n0 * KDIM;

    // ---- ldmatrix addressing: base + t4*2048 + per-kstep XOR term ----
    uint32_t swz = (uint32_t)(lane & 7);
    uint32_t hi = (uint32_t)(lane >> 4);            // A k-half select
    uint32_t piece = (uint32_t)((lane >> 3) & 1);   // B k-half select
    uint32_t a0 = (uint32_t)((wm * 64 + (lane & 15)) * 128);
    uint32_t b0 = (uint32_t)((wn * 64 + (lane & 7) + ((lane >> 4) << 3)) * 128);

    float acc[4][8][4];
#pragma unroll
    for (int a = 0; a < 4; a++)
#pragma unroll
        for (int b = 0; b < 8; b++)
#pragma unroll
            for (int c = 0; c < 4; c++) acc[a][b][c] = 0.0f;

    // ---- stage issue (16 cp.async per thread, strided addressing) ----
    auto issue_stage = [&](int k0h, uint32_t sOff) {
        const __half* sa = baseA + srcOff0 + k0h;
        const __half* sb = baseB + srcOff0 + k0h;
        uint32_t da = smem_u32 + sOff + dst0;
        uint32_t db = da + STAGE_A;
#pragma unroll
        for (int i = 0; i < 8; i++)
            cp16(da + i * 2048u, sa + (size_t)i * 16 * KDIM);
#pragma unroll
        for (int i = 0; i < 8; i++)
            cp16(db + i * 2048u, sb + (size_t)i * 16 * KDIM);
        asm volatile("cp.async.commit_group;\n" ::: "memory");
    };

    issue_stage(0, 0);
    issue_stage(64, STAGE_BYTES);

    uint32_t fA[2][4][4], fB[2][4][4];

#pragma unroll 1
    for (int k = 0; k < KT; k++) {
        if (k < KT - 1) asm volatile("cp.async.wait_group 1;\n" ::: "memory");
        else            asm volatile("cp.async.wait_group 0;\n" ::: "memory");
        __syncthreads();

        uint32_t sA = smem_u32 + (uint32_t)(k % STAGES) * STAGE_BYTES;
        uint32_t sB = sA + STAGE_A;

        // prime kstep 0 fragments
        LDSM_FRAGS(fA[0], fB[0], sA, sB, 0u);

#pragma unroll
        for (int ks = 0; ks < 4; ks++) {
            int cb = ks & 1, nb = cb ^ 1;
            if (ks < 3) {
                LDSM_FRAGS(fA[nb], fB[nb], sA, sB, (uint32_t)((ks + 1) << 1));
            } else if (k + 2 < KT) {
                issue_stage((k + 2) * 64, (uint32_t)((k + 2) % STAGES) * STAGE_BYTES);
            }
            MMA_BURST(fA[cb], fB[cb]);
        }
    }

    // -------- epilogue: acc -> smem (transpose to n-contiguous) --------
    __syncthreads();   // all compute done; stage smem now reusable
#pragma unroll
    for (int t4 = 0; t4 < 4; t4++) {
#pragma unroll
        for (int p = 0; p < 4; p++) {
            int r0 = wm * 64 + t4 * 16 + (lane >> 2);
            int c0 = wn * 64 + p * 16 + (lane & 3) * 2;
            *(float2*)&smemf[r0 * EPI_STRIDE + c0]            = make_float2(acc[t4][2 * p][0], acc[t4][2 * p][1]);
            *(float2*)&smemf[(r0 + 8) * EPI_STRIDE + c0]      = make_float2(acc[t4][2 * p][2], acc[t4][2 * p][3]);
            *(float2*)&smemf[r0 * EPI_STRIDE + c0 + 8]        = make_float2(acc[t4][2 * p + 1][0], acc[t4][2 * p + 1][1]);
            *(float2*)&smemf[(r0 + 8) * EPI_STRIDE + c0 + 8]  = make_float2(acc[t4][2 * p + 1][2], acc[t4][2 * p + 1][3]);
        }
    }
    __syncthreads();

    // -------- fused LSTM: gates -> h_t, c_t --------
    int r = tid;                      // 0..127 (batch row within tile)
    int mrow = m0 + r;
    int hglob0 = nt * 32;             // this block's head range (BN/4 = 32 heads)
    const float* cpr = c_prev + (size_t)mrow * HSZ + hglob0;
    float* hout = out + (size_t)mrow * HSZ + hglob0;
    float* cout = out + (size_t)BATCH * HSZ + (size_t)mrow * HSZ + hglob0;
    const float* biasf = (const float*)(smem + BIAS_OFF);
#pragma unroll
    for (int g4 = 0; g4 < 8; g4++) {
        int hl = g4 * 4;                               // local head base
        float4 cp4 = *(const float4*)(cpr + hl);
        float cpv[4] = {cp4.x, cp4.y, cp4.z, cp4.w};
        float hv[4], cv[4];
#pragma unroll
        for (int j = 0; j < 4; j++) {
            const float* gt = &smemf[r * EPI_STRIDE + (hl + j) * 4];
            const float* bs = &biasf[(hl + j) * 4];
            float gf = gt[0] + bs[0];
            float gi = gt[1] + bs[1];
            float gc = gt[2] + bs[2];
            float go = gt[3] + bs[3];
            float f  = sigmoidf_(gf);
            float iv = sigmoidf_(gi);
            float ct = tanhf_(gc);
            float o  = sigmoidf_(go);
            float cn = fmaf(f, cpv[j], iv * ct);
            cv[j] = cn;
            hv[j] = o * tanhf_(cn);
        }
        *(float4*)(hout + hl) = make_float4(hv[0], hv[1], hv[2], hv[3]);
        *(float4*)(cout + hl) = make_float4(cv[0], cv[1], cv[2], cv[3]);
    }
}

// ---------------- launch ----------------
extern "C" void kernel_launch(void* const* d_in, const int* in_sizes, int n_in,
                              void* d_out, int out_size) {
    const float* x  = (const float*)d_in[0];
    const float* h  = (const float*)d_in[1];
    const float* c  = (const float*)d_in[2];
    const float* Wf = (const float*)d_in[3];
    const float* bf = (const float*)d_in[4];
    const float* Wi = (const float*)d_in[5];
    const float* bi = (const float*)d_in[6];
    const float* Wc = (const float*)d_in[7];
    const float* bc = (const float*)d_in[8];
    const float* Wo = (const float*)d_in[9];
    const float* bo = (const float*)d_in[10];
    float* out = (float*)d_out;

    conv_a_kernel<<<(BATCH * KDIM / 4) / 256, 256>>>(x, h);
    conv_w_kernel<<<(NDIM * KDIM / 4) / 256, 256>>>(Wf, Wi, Wc, Wo);
    conv_b_kernel<<<NDIM / 256, 256>>>(bf, bi, bc, bo);

    static int smem_set = 0;
    if (!smem_set) {
        cudaFuncSetAttribute(lstm_gemm_kernel,
                             cudaFuncAttributeMaxDynamicSharedMemorySize, SMEM_TOTAL);
        smem_set = 1;
    }
    lstm_gemm_kernel<<<(BATCH / BM) * (NDIM / BN), NTHREADS, SMEM_TOTAL>>>(c, out);
}